// round 15
// baseline (speedup 1.0000x reference)
#include <cuda_runtime.h>
#include <cuda_fp16.h>
#include <math.h>

// Problem dims (fixed): B=4096, T=8, CH_IN=2048, C=1024, N=512, K=5, EPS=1e-8

__device__ __half g_kvh[4096u * 2048u];          // [k | v] fp16 (GEMM out)
__device__ __half g_E2 [5u * 512u * 2048u];      // [EkT | EvT] [z][n][j], fp16 (bias added)
__device__ __half g_Ev [5u * 1024u * 512u];      // Ev  [z][c][n], fp16 (from E2 transpose)
__device__ __half g_simh[4096u * 5u * 512u];     // sim fp16 (raw k.Ek, unnormalized)
__device__ __half g_wh [4096u * 5u * 512u];      // softmax weights fp16
__device__ __half g_feh[5u * 4096u * 1024u];     // feature_E fp16, [z][b][c]
__device__ float  g_invE[5u * 512u];             // 1/max(||Ek col||, eps)
__device__ float  g_invK[4096u];                 // 1/max(||k row||, eps)
__device__ __half g_xl [4096u * 2048u];          // x_last fp16
__device__ __half g_wtf[4u * 1024u * 2048u];     // Wk|Wv|WEk|WEv fp16 (contiguous)
__device__ __half g_stT[5u * 512u * 2048u];      // static transposed [z][n][i] fp16
__device__ float  g_bkv[2048u];                  // bk | bv
__device__ float  g_bE2[2048u];                  // bEk | bEv

#define DINLINE __device__ __forceinline__

DINLINE void mma_f16(float* c, const unsigned* a, const unsigned* b) {
    asm volatile(
        "mma.sync.aligned.m16n8k16.row.col.f32.f16.f16.f32 "
        "{%0,%1,%2,%3}, {%4,%5,%6,%7}, {%8,%9}, {%0,%1,%2,%3};"
        : "+f"(c[0]), "+f"(c[1]), "+f"(c[2]), "+f"(c[3])
        : "r"(a[0]), "r"(a[1]), "r"(a[2]), "r"(a[3]),
          "r"(b[0]), "r"(b[1]));
}

DINLINE void ldsm4(unsigned& r0, unsigned& r1, unsigned& r2, unsigned& r3, unsigned saddr) {
    asm volatile("ldmatrix.sync.aligned.m8n8.x4.shared.b16 {%0,%1,%2,%3}, [%4];"
                 : "=r"(r0), "=r"(r1), "=r"(r2), "=r"(r3) : "r"(saddr));
}

DINLINE void cp16(void* dst_smem, const void* src) {
    unsigned d = (unsigned)__cvta_generic_to_shared(dst_smem);
    asm volatile("cp.async.cg.shared.global [%0], [%1], 16;" :: "r"(d), "l"(src));
}
DINLINE void cp_commit() { asm volatile("cp.async.commit_group;"); }
DINLINE void cp_wait2()  { asm volatile("cp.async.wait_group 2;"); }
DINLINE void cp_wait0()  { asm volatile("cp.async.wait_group 0;"); }

// ---------------------------------------------------------------------------
// FP16 NT GEMM body (C = A * B^T), fp32 accumulate. cp.async 4-stage + ldmatrix.
// 128x128x32 CTA tile, 128 threads = 4 warps (2x2), warp tile 64x64.
// SMEM rows stride 40 halves (80B) -> ldmatrix conflict-free, cp16-aligned.
// C is __half (bias added in fp32, then rounded).
// ---------------------------------------------------------------------------
DINLINE void gemm_body(const __half* __restrict__ A, long lda,
                       const __half* __restrict__ Bm, long ldb,
                       __half* __restrict__ Cm, long ldc,
                       int Kd, const float* __restrict__ bias_n,
                       int m0, int n0, char* smem)
{
    constexpr int ST = 40;
    constexpr unsigned ABYTES = 128 * ST * 2;  // 10240
    constexpr unsigned STAGE  = 2 * ABYTES;    // 20480

    const unsigned shb = (unsigned)__cvta_generic_to_shared(smem);
    const int tid  = threadIdx.x;
    const int lane = tid & 31;
    const int wid  = tid >> 5;                 // 0..3
    const int g  = lane >> 2;
    const int tg = lane & 3;
    const int m_w = (wid & 1) * 64;
    const int n_w = (wid >> 1) * 64;

    const int rr = lane & 7, q = lane >> 3;
    const int arow = ((q & 1) << 3) + rr;
    const int acol = (q >> 1) << 3;
    const int brow = ((q >> 1) << 3) + rr;
    const int bcol = (q & 1) << 3;

    unsigned aoff[4], boff[4];
#pragma unroll
    for (int mt = 0; mt < 4; mt++)
        aoff[mt] = ((m_w + mt * 16 + arow) * ST + acol) * 2;
#pragma unroll
    for (int nt2 = 0; nt2 < 4; nt2++)
        boff[nt2] = ABYTES + ((n_w + nt2 * 16 + brow) * ST + bcol) * 2;

    float acc[4][8][4];
#pragma unroll
    for (int i = 0; i < 4; i++)
#pragma unroll
        for (int j = 0; j < 8; j++)
#pragma unroll
            for (int p = 0; p < 4; p++) acc[i][j][p] = 0.f;

    auto issue = [&](int t) {
        const int kt = t << 5;
        char* stg = smem + (unsigned)(t & 3) * STAGE;
#pragma unroll
        for (int i = 0; i < 4; i++) {
            int lin = i * 128 + tid;
            int r = lin >> 2, c = lin & 3;
            cp16(stg + r * 80 + c * 16, A + (long)(m0 + r) * lda + kt + c * 8);
        }
#pragma unroll
        for (int i = 0; i < 4; i++) {
            int lin = i * 128 + tid;
            int r = lin >> 2, c = lin & 3;
            cp16(stg + ABYTES + r * 80 + c * 16, Bm + (long)(n0 + r) * ldb + kt + c * 8);
        }
        cp_commit();
    };

    const int KT = Kd >> 5;
    issue(0);
    issue(1);
    issue(2);

    for (int t = 0; t < KT; t++) {
        cp_wait2();
        __syncthreads();
        int tn = t + 3;
        if (tn < KT) issue(tn); else cp_commit();

        const unsigned stb = shb + (unsigned)(t & 3) * STAGE;
#pragma unroll
        for (int s = 0; s < 2; s++) {
            const unsigned kb = s * 32;
            unsigned af[4][4], bf[8][2];
#pragma unroll
            for (int mt = 0; mt < 4; mt++)
                ldsm4(af[mt][0], af[mt][1], af[mt][2], af[mt][3], stb + aoff[mt] + kb);
#pragma unroll
            for (int nt2 = 0; nt2 < 4; nt2++)
                ldsm4(bf[2 * nt2][0], bf[2 * nt2][1],
                      bf[2 * nt2 + 1][0], bf[2 * nt2 + 1][1], stb + boff[nt2] + kb);
#pragma unroll
            for (int mt = 0; mt < 4; mt++)
#pragma unroll
                for (int nt = 0; nt < 8; nt++)
                    mma_f16(acc[mt][nt], af[mt], bf[nt]);
        }
    }
    cp_wait0();

#pragma unroll
    for (int mt = 0; mt < 4; mt++) {
        int r0 = m0 + m_w + mt * 16 + g;
#pragma unroll
        for (int nt = 0; nt < 8; nt++) {
            int cc = n0 + n_w + nt * 8 + 2 * tg;
            float bn0 = bias_n ? bias_n[cc]     : 0.f;
            float bn1 = bias_n ? bias_n[cc + 1] : 0.f;
            const float* c = acc[mt][nt];
            *(__half2*)(Cm + (long)r0 * ldc + cc) =
                __floats2half2_rn(c[0] + bn0, c[1] + bn1);
            *(__half2*)(Cm + (long)(r0 + 8) * ldc + cc) =
                __floats2half2_rn(c[2] + bn0, c[3] + bn1);
        }
    }
}

// Generic batched NT GEMM (used for fe).
__global__ __launch_bounds__(128, 2)
void gemm_h(const __half* __restrict__ A, long lda, long sAz,
            const __half* __restrict__ Bm, long ldb, long sBz,
            __half* __restrict__ Cm, long ldc, long sCz,
            int Kd, const float* __restrict__ bias_n)
{
    extern __shared__ char smem[];
    gemm_body(A + (long)blockIdx.z * sAz, lda,
              Bm + (long)blockIdx.z * sBz, ldb,
              Cm + (long)blockIdx.z * sCz, ldc,
              Kd, bias_n, blockIdx.y * 128, blockIdx.x * 128, smem);
}

// Fused launch: kv GEMM (y<32) + E2 GEMM (y>=32, z=(y-32)/4). K=2048 both.
__global__ __launch_bounds__(128, 2)
void gemm_dual(const __half* __restrict__ xl, const __half* __restrict__ wkv,
               __half* __restrict__ kvh, const float* __restrict__ bkv,
               const __half* __restrict__ stT, const __half* __restrict__ wE,
               __half* __restrict__ E2, const float* __restrict__ bE2)
{
    extern __shared__ char smem[];
    const int y = blockIdx.y;
    if (y < 32) {
        gemm_body(xl, 2048, wkv, 2048, kvh, 2048,
                  2048, bkv, y * 128, blockIdx.x * 128, smem);
    } else {
        int idx = y - 32;
        int z = idx >> 2, my = idx & 3;
        gemm_body(stT + (long)z * 512 * 2048, 2048, wE, 2048,
                  E2 + (long)z * 512 * 2048, 2048,
                  2048, bE2, my * 128, blockIdx.x * 128, smem);
    }
}

// ---------------------------------------------------------------------------
// Heterogeneous launch: sim GEMM tiles + post-GEMM1 elementwise work.
//   t < 640          : sim tile (tx=t&3, ty=(t>>2)&31, tz=t>>7)
//   640..3199 (2560) : transpose_Ev  (EvT part of E2 -> Ev [z][c][n])
//   3200..5759 (2560): ssqE          (inv col norms of Ek rows)
//   5760..9855 (4096): invK          (inv row norms of k)
// 128 threads everywhere.
// ---------------------------------------------------------------------------
__global__ __launch_bounds__(128, 2)
void sim_post_kernel(const __half* __restrict__ kvh,
                     const __half* __restrict__ E2,
                     __half* __restrict__ simh,
                     __half* __restrict__ Ev,
                     float* __restrict__ invE,
                     float* __restrict__ invK)
{
    extern __shared__ char smem[];
    const int blk = blockIdx.x, tid = threadIdx.x;

    if (blk < 640) {                                    // sim GEMM tile
        int tx = blk & 3, ty = (blk >> 2) & 31, tz = blk >> 7;
        gemm_body(kvh, 2048,
                  E2 + (long)tz * 512 * 2048, 2048,
                  simh + (long)tz * 512, 5 * 512,
                  1024, nullptr, ty * 128, tx * 128, smem);
    } else if (blk < 3200) {                            // transpose_Ev
        __half (*htile)[33] = (__half(*)[33])smem;
        int t = blk - 640;
        int z = t >> 9;
        int rem = t & 511;
        int c0 = (rem >> 4) * 32;
        int n0 = (rem & 15) * 32;
        int txx = tid & 31, tyy = tid >> 5;             // 32 x 4
        const __half* src = E2 + (long)z * 512 * 2048 + 1024;
        __half* dst = Ev + (long)z * 1024 * 512;
#pragma unroll
        for (int d = 0; d < 8; d++) {
            int n = n0 + tyy + d * 4;
            htile[tyy + d * 4][txx] = src[(long)n * 2048 + c0 + txx];
        }
        __syncthreads();
#pragma unroll
        for (int d = 0; d < 8; d++) {
            int c = c0 + tyy + d * 4;
            dst[(long)c * 512 + n0 + txx] = htile[txx][tyy + d * 4];
        }
    } else if (blk < 5760) {                            // ssqE
        float* red = (float*)smem;
        int row = blk - 3200;
        const __half2* base = (const __half2*)(E2 + (long)row * 2048);
        float s = 0.f;
#pragma unroll
        for (int i = 0; i < 4; i++) {
            float2 a = __half22float2(base[tid * 4 + i]);
            s += a.x * a.x + a.y * a.y;
        }
        red[tid] = s;
        __syncthreads();
        for (int st = 64; st > 0; st >>= 1) {
            if (tid < st) red[tid] += red[tid + st];
            __syncthreads();
        }
        if (tid == 0) invE[row] = 1.f / fmaxf(sqrtf(red[0]), 1e-8f);
    } else {                                            // invK
        float* red = (float*)smem;
        int b = blk - 5760;
        const __half2* row = (const __half2*)(kvh + (long)b * 2048);
        float s = 0.f;
#pragma unroll
        for (int i = 0; i < 4; i++) {
            float2 a = __half22float2(row[tid * 4 + i]);
            s += a.x * a.x + a.y * a.y;
        }
        red[tid] = s;
        __syncthreads();
        for (int st = 64; st > 0; st >>= 1) {
            if (tid < st) red[tid] += red[tid + st];
            __syncthreads();
        }
        if (tid == 0) invK[b] = 1.f / fmaxf(sqrtf(red[0]), 1e-8f);
    }
}

// ---------------------------------------------------------------------------
// Fused preprocessing: gather_x | cvt_w | biases | transpose_static.
// ---------------------------------------------------------------------------
__global__ __launch_bounds__(256)
void prep_kernel(const float* __restrict__ x,
                 const float* __restrict__ Wk, const float* __restrict__ Wv,
                 const float* __restrict__ WEk, const float* __restrict__ WEv,
                 const float* __restrict__ bk, const float* __restrict__ bv,
                 const float* __restrict__ bEk, const float* __restrict__ bEv,
                 const float* __restrict__ stat,
                 __half2* __restrict__ xl, __half2* __restrict__ wtf,
                 float* __restrict__ bkv, float* __restrict__ bE2,
                 __half* __restrict__ stT)
{
    __shared__ float tile[32][33];
    const int blk = blockIdx.x, tid = threadIdx.x;

    if (blk < 8192) {                                   // gather_x
        int i = blk * 256 + tid;
        int b  = i >> 9;
        int c4 = (i & 511) * 4;
        float4 v = *(const float4*)(x + (long)b * 16384 + 14336 + c4);
        xl[(long)b * 1024 + (i & 511) * 2]     = __floats2half2_rn(v.x, v.y);
        xl[(long)b * 1024 + (i & 511) * 2 + 1] = __floats2half2_rn(v.z, v.w);
    } else if (blk < 16384) {                           // cvt_w
        int j = (blk - 8192) * 256 + tid;
        int m = j >> 19;
        int i = j & 0x7FFFF;
        const float* src = (m == 0) ? Wk : (m == 1) ? Wv : (m == 2) ? WEk : WEv;
        float4 v = ((const float4*)src)[i];
        __half2* dst = wtf + (long)m * 1048576 + 2 * i;
        dst[0] = __floats2half2_rn(v.x, v.y);
        dst[1] = __floats2half2_rn(v.z, v.w);
    } else if (blk < 16400) {                           // biases
        int i = (blk - 16384) * 256 + tid;              // 0..4095
        if (i < 2048) bkv[i] = (i < 1024) ? bk[i] : bv[i - 1024];
        else {
            int j = i - 2048;
            bE2[j] = (j < 1024) ? bEk[j] : bEv[j - 1024];
        }
    } else {                                            // transpose_static
        int t = blk - 16400;                            // 0..5119
        int z = t >> 10;
        int rem = t & 1023;
        int i0 = (rem & 63) * 32;
        int n0 = (rem >> 6) * 32;
        int tx = tid & 31, ty = tid >> 5;
        const float* src = stat + (long)z * 2048 * 512;
        __half* dst = stT + (long)z * 512 * 2048;
#pragma unroll
        for (int d = 0; d < 4; d++) {
            int row = i0 + ty + d * 8;
            tile[ty + d * 8][tx] = src[(long)row * 512 + n0 + tx];
        }
        __syncthreads();
#pragma unroll
        for (int d = 0; d < 4; d++) {
            int n = n0 + ty + d * 8;
            dst[(long)n * 2048 + i0 + tx] = __float2half_rn(tile[tx][ty + d * 8]);
        }
    }
}

// ---------------------------------------------------------------------------
// Warp-per-row softmax: scale by invK[b]*invE[z,:], softmax over 512,
// fp16 in/out. 256 threads = 8 warps = 8 rows per block; grid = 20480/8.
// All reductions via shfl (zero barriers); __expf (MUFU-based).
// ---------------------------------------------------------------------------
__global__ __launch_bounds__(256)
void softmax_kernel(const __half* __restrict__ S, const float* __restrict__ invE,
                    const float* __restrict__ invK, __half* __restrict__ W)
{
    const int lane = threadIdx.x & 31;
    const int row  = blockIdx.x * 8 + (threadIdx.x >> 5);
    const int z = row % 5;
    const float ik = invK[row / 5];

    const float4* base = (const float4*)(S + (long)row * 512);   // 4 half2 per float4
    const float4* esrc = (const float4*)(invE + z * 512);

    // load 16 logits (4 float4 = 8 half2), scale
    float v[16];
#pragma unroll
    for (int i = 0; i < 2; i++) {
        float4 hv = base[lane * 2 + i];                 // 8 halves
        const __half2* h2 = (const __half2*)&hv;
        float4 e0 = esrc[(lane * 2 + i) * 2];
        float4 e1 = esrc[(lane * 2 + i) * 2 + 1];
        const float* ep = (const float*)&e0;
        const float* ep1 = (const float*)&e1;
#pragma unroll
        for (int j = 0; j < 4; j++) {
            float2 f = __half22float2(h2[j]);
            float s0 = (j < 2) ? ep[2 * j]     : ep1[2 * (j - 2)];
            float s1 = (j < 2) ? ep[2 * j + 1] : ep1[2 * (j - 2) + 1];
            v[i * 8 + 2 * j]     = f.x * s0 * ik;
            v[i * 8 + 2 * j + 1] = f.y * s1 * ik;
        }
    }

    float m = v[0];
#pragma unroll
    for (int i = 1; i < 16; i++) m = fmaxf(m, v[i]);
#pragma unroll
    for (int o = 16; o > 0; o >>= 1) m = fmaxf(m, __shfl_xor_sync(0xFFFFFFFFu, m, o));

    float s = 0.f;
#pragma unroll
    for (int i = 0; i < 16; i++) { v[i] = __expf(v[i] - m); s += v[i]; }
#pragma unroll
    for (int o = 16; o > 0; o >>= 1) s += __shfl_xor_sync(0xFFFFFFFFu, s, o);
    float inv = __fdividef(1.f, s);

    __half2 ov[8];
#pragma unroll
    for (int j = 0; j < 8; j++)
        ov[j] = __floats2half2_rn(v[2 * j] * inv, v[2 * j + 1] * inv);
    float4* dst = (float4*)(W + (long)row * 512);
    dst[lane * 2]     = *(float4*)&ov[0];
    dst[lane * 2 + 1] = *(float4*)&ov[4];
}

// ---------------------------------------------------------------------------
// Final stage: gate + concat + output GEMV. grid = B/16, 256 threads.
// ---------------------------------------------------------------------------
__global__ __launch_bounds__(256)
void final_kernel(const __half* __restrict__ kvh,
                  const __half* __restrict__ feh,
                  const float* __restrict__ Ww,
                  const float* __restrict__ bw,
                  const float* __restrict__ Wout,
                  const float* __restrict__ bout,
                  float* __restrict__ out)
{
    const int tid = threadIdx.x, lane = tid & 31, wid = tid >> 5;
    const int c0 = tid * 4;
    const long sz = (long)4096 * 1024;

    float ww[4];
    float wv[5][4], wf[5][4];
    *(float4*)ww = *(const float4*)&Ww[c0];
#pragma unroll
    for (int kk = 0; kk < 5; kk++) {
        *(float4*)wv[kk] = *(const float4*)&Wout[kk * 2048 + c0];
        *(float4*)wf[kk] = *(const float4*)&Wout[kk * 2048 + 1024 + c0];
    }
    const float bwv = bw[0];

    __shared__ float wred[5][8];
    __shared__ float s_fw[5];

    for (int bi = 0; bi < 16; bi++) {
        const int b = blockIdx.x * 16 + bi;
        const long bc = (long)b * 1024 + c0;

        float fe[5][4];
#pragma unroll
        for (int kk = 0; kk < 5; kk++) {
            __half2 h0 = *(const __half2*)(feh + sz * kk + bc);
            __half2 h1 = *(const __half2*)(feh + sz * kk + bc + 2);
            float2 f0 = __half22float2(h0), f1 = __half22float2(h1);
            fe[kk][0] = f0.x; fe[kk][1] = f0.y; fe[kk][2] = f1.x; fe[kk][3] = f1.y;
        }
        __half2 v0 = *(const __half2*)(kvh + (long)b * 2048 + 1024 + c0);
        __half2 v1 = *(const __half2*)(kvh + (long)b * 2048 + 1024 + c0 + 2);
        float2 vf0 = __half22float2(v0), vf1 = __half22float2(v1);

        float acc[5];
#pragma unroll
        for (int kk = 0; kk < 5; kk++) {
            float s = fe[kk][0] * ww[0] + fe[kk][1] * ww[1]
                    + fe[kk][2] * ww[2] + fe[kk][3] * ww[3];
#pragma unroll
            for (int o = 16; o > 0; o >>= 1) s += __shfl_xor_sync(0xFFFFFFFFu, s, o);
            acc[kk] = s;
        }
        if (lane == 0) {
#pragma unroll
            for (int kk = 0; kk < 5; kk++) wred[kk][wid] = acc[kk];
        }
        __syncthreads();
        if (tid < 5) {
            float s = 0.f;
#pragma unroll
            for (int w = 0; w < 8; w++) s += wred[tid][w];
            s_fw[tid] = 1.f / (1.f + __expf(-(s + bwv)));
        }
        __syncthreads();
        float fwl[5];
#pragma unroll
        for (int kk = 0; kk < 5; kk++) fwl[kk] = s_fw[kk];

        float fE[4];
#pragma unroll
        for (int qq = 0; qq < 4; qq++) {
            float s = 0.f;
#pragma unroll
            for (int kk = 0; kk < 5; kk++) s = fmaf(fe[kk][qq], fwl[kk], s);
            fE[qq] = fmaxf(s, 0.f);
        }
        float hv[4] = {fmaxf(vf0.x, 0.f), fmaxf(vf0.y, 0.f),
                       fmaxf(vf1.x, 0.f), fmaxf(vf1.y, 0.f)};

        float oacc[5];
#pragma unroll
        for (int kk = 0; kk < 5; kk++) {
            float s = hv[0] * wv[kk][0] + hv[1] * wv[kk][1]
                    + hv[2] * wv[kk][2] + hv[3] * wv[kk][3]
                    + fE[0] * wf[kk][0] + fE[1] * wf[kk][1]
                    + fE[2] * wf[kk][2] + fE[3] * wf[kk][3];
#pragma unroll
            for (int o = 16; o > 0; o >>= 1) s += __shfl_xor_sync(0xFFFFFFFFu, s, o);
            oacc[kk] = s;
        }
        if (lane == 0) {
#pragma unroll
            for (int kk = 0; kk < 5; kk++) wred[kk][wid] = oacc[kk];
        }
        __syncthreads();
        if (tid < 5) {
            float s = 0.f;
#pragma unroll
            for (int w = 0; w < 8; w++) s += wred[tid][w];
            out[b * 5 + tid] = s + bout[tid];
        }
        __syncthreads();
    }
}

extern "C" void kernel_launch(void* const* d_in, const int* in_sizes, int n_in,
                              void* d_out, int out_size)
{
    const float* x    = (const float*)d_in[0];   // (4096, 8, 2048)
    const float* stat = (const float*)d_in[1];   // (5, 2048, 512)
    const float* Wk   = (const float*)d_in[2];   // (1024, 2048)
    const float* bk   = (const float*)d_in[3];
    const float* Wv   = (const float*)d_in[4];
    const float* bv   = (const float*)d_in[5];
    const float* WEk  = (const float*)d_in[6];
    const float* bEk  = (const float*)d_in[7];
    const float* WEv  = (const float*)d_in[8];
    const float* bEv  = (const float*)d_in[9];
    const float* Ww   = (const float*)d_in[10];
    const float* bw   = (const float*)d_in[11];
    const float* Wout = (const float*)d_in[12];  // (5, 2048)
    const float* bout = (const float*)d_in[13];
    float* out = (float*)d_out;                  // (4096, 5, 1)

    float *invE_, *invK_, *bkv_, *bE2_;
    __half *kvh_, *E2_, *Ev_, *simh_, *wh_, *feh_, *xl_, *wtf_, *stT_;
    cudaGetSymbolAddress((void**)&kvh_, g_kvh);
    cudaGetSymbolAddress((void**)&E2_,  g_E2);
    cudaGetSymbolAddress((void**)&Ev_,  g_Ev);
    cudaGetSymbolAddress((void**)&simh_, g_simh);
    cudaGetSymbolAddress((void**)&wh_,  g_wh);
    cudaGetSymbolAddress((void**)&feh_, g_feh);
    cudaGetSymbolAddress((void**)&invE_, g_invE);
    cudaGetSymbolAddress((void**)&invK_, g_invK);
    cudaGetSymbolAddress((void**)&xl_,  g_xl);
    cudaGetSymbolAddress((void**)&wtf_, g_wtf);
    cudaGetSymbolAddress((void**)&stT_, g_stT);
    cudaGetSymbolAddress((void**)&bkv_, g_bkv);
    cudaGetSymbolAddress((void**)&bE2_, g_bE2);

    constexpr int SMEM = 4 * 2 * 128 * 40 * 2;   // 81920 B (4 stages)
    cudaFuncSetAttribute(gemm_h,          cudaFuncAttributeMaxDynamicSharedMemorySize, SMEM);
    cudaFuncSetAttribute(gemm_dual,       cudaFuncAttributeMaxDynamicSharedMemorySize, SMEM);
    cudaFuncSetAttribute(sim_post_kernel, cudaFuncAttributeMaxDynamicSharedMemorySize, SMEM);

    // 1. fused preprocessing
    prep_kernel<<<21520, 256>>>(x, Wk, Wv, WEk, WEv, bk, bv, bEk, bEv, stat,
                                (__half2*)xl_, (__half2*)wtf_, bkv_, bE2_, stT_);

    // 2. fused kv + E2 GEMM (832 CTAs, K=2048)
    gemm_dual<<<dim3(16, 52), 128, SMEM>>>(xl_, wtf_, kvh_, bkv_,
                                           stT_, wtf_ + 2L * 1024 * 2048, E2_, bE2_);

    // 3. heterogeneous: sim GEMM (640 tiles) + transpose_Ev + ssqE + invK
    sim_post_kernel<<<9856, 128, SMEM>>>(kvh_, E2_, simh_, Ev_, invE_, invK_);

    // 4. warp-per-row softmax with invK*invE logit scaling
    softmax_kernel<<<2560, 256>>>(simh_, invE_, invK_, wh_);

    // 5. fe = w @ Ev^T (NT, 4096x1024x512, z=5), fp16 out
    gemm_h<<<dim3(8, 32, 5), 128, SMEM>>>(wh_, 5 * 512, 512,
                                          Ev_, 512, (long)1024 * 512,
                                          feh_, 1024, (long)4096 * 1024, 512, nullptr);

    // 6. gate + output
    final_kernel<<<256, 256>>>(kvh_, feh_, Ww, bw, Wout, bout, out);
}

// round 17
// speedup vs baseline: 1.5383x; 1.5383x over previous
#include <cuda_runtime.h>
#include <cuda_fp16.h>
#include <math.h>

// Problem dims (fixed): B=4096, T=8, CH_IN=2048, C=1024, N=512, K=5, EPS=1e-8

__device__ __half g_kvh[4096u * 2048u];          // [k | v] fp16 (GEMM out)
__device__ __half g_E2 [5u * 512u * 2048u];      // [EkT | EvT] [z][n][j], fp16 (bias added)
__device__ __half g_Ev [5u * 1024u * 512u];      // Ev  [z][c][n], fp16 (from E2 transpose)
__device__ __half g_simh[4096u * 5u * 512u];     // sim fp16 (raw k.Ek, unnormalized)
__device__ __half g_wh [4096u * 5u * 512u];      // softmax weights fp16
__device__ __half g_feh[5u * 4096u * 1024u];     // feature_E fp16, [z][b][c]
__device__ float  g_invE[5u * 512u];             // 1/max(||Ek col||, eps)
__device__ float  g_invK[4096u];                 // 1/max(||k row||, eps)
__device__ __half g_xl [4096u * 2048u];          // x_last fp16
__device__ __half g_wtf[4u * 1024u * 2048u];     // Wk|Wv|WEk|WEv fp16 (contiguous)
__device__ __half g_stT[5u * 512u * 2048u];      // static transposed [z][n][i] fp16
__device__ float  g_bkv[2048u];                  // bk | bv
__device__ float  g_bE2[2048u];                  // bEk | bEv

#define DINLINE __device__ __forceinline__

DINLINE void mma_f16(float* c, const unsigned* a, const unsigned* b) {
    asm volatile(
        "mma.sync.aligned.m16n8k16.row.col.f32.f16.f16.f32 "
        "{%0,%1,%2,%3}, {%4,%5,%6,%7}, {%8,%9}, {%0,%1,%2,%3};"
        : "+f"(c[0]), "+f"(c[1]), "+f"(c[2]), "+f"(c[3])
        : "r"(a[0]), "r"(a[1]), "r"(a[2]), "r"(a[3]),
          "r"(b[0]), "r"(b[1]));
}

DINLINE void ldsm4(unsigned& r0, unsigned& r1, unsigned& r2, unsigned& r3, unsigned saddr) {
    asm volatile("ldmatrix.sync.aligned.m8n8.x4.shared.b16 {%0,%1,%2,%3}, [%4];"
                 : "=r"(r0), "=r"(r1), "=r"(r2), "=r"(r3) : "r"(saddr));
}

DINLINE void cp16(void* dst_smem, const void* src) {
    unsigned d = (unsigned)__cvta_generic_to_shared(dst_smem);
    asm volatile("cp.async.cg.shared.global [%0], [%1], 16;" :: "r"(d), "l"(src));
}
DINLINE void cp_commit() { asm volatile("cp.async.commit_group;"); }
DINLINE void cp_wait2()  { asm volatile("cp.async.wait_group 2;"); }
DINLINE void cp_wait0()  { asm volatile("cp.async.wait_group 0;"); }

// ---------------------------------------------------------------------------
// FP16 NT GEMM body (C = A * B^T), fp32 accumulate. cp.async 4-stage + ldmatrix.
// 128x128x32 CTA tile, 128 threads = 4 warps (2x2), warp tile 64x64.
// SMEM rows stride 40 halves (80B) -> ldmatrix conflict-free, cp16-aligned.
// C is __half (bias added in fp32, then rounded).
// ---------------------------------------------------------------------------
DINLINE void gemm_body(const __half* __restrict__ A, long lda,
                       const __half* __restrict__ Bm, long ldb,
                       __half* __restrict__ Cm, long ldc,
                       int Kd, const float* __restrict__ bias_n,
                       int m0, int n0, char* smem)
{
    constexpr int ST = 40;
    constexpr unsigned ABYTES = 128 * ST * 2;  // 10240
    constexpr unsigned STAGE  = 2 * ABYTES;    // 20480

    const unsigned shb = (unsigned)__cvta_generic_to_shared(smem);
    const int tid  = threadIdx.x;
    const int lane = tid & 31;
    const int wid  = tid >> 5;                 // 0..3
    const int g  = lane >> 2;
    const int tg = lane & 3;
    const int m_w = (wid & 1) * 64;
    const int n_w = (wid >> 1) * 64;

    const int rr = lane & 7, q = lane >> 3;
    const int arow = ((q & 1) << 3) + rr;
    const int acol = (q >> 1) << 3;
    const int brow = ((q >> 1) << 3) + rr;
    const int bcol = (q & 1) << 3;

    unsigned aoff[4], boff[4];
#pragma unroll
    for (int mt = 0; mt < 4; mt++)
        aoff[mt] = ((m_w + mt * 16 + arow) * ST + acol) * 2;
#pragma unroll
    for (int nt2 = 0; nt2 < 4; nt2++)
        boff[nt2] = ABYTES + ((n_w + nt2 * 16 + brow) * ST + bcol) * 2;

    float acc[4][8][4];
#pragma unroll
    for (int i = 0; i < 4; i++)
#pragma unroll
        for (int j = 0; j < 8; j++)
#pragma unroll
            for (int p = 0; p < 4; p++) acc[i][j][p] = 0.f;

    auto issue = [&](int t) {
        const int kt = t << 5;
        char* stg = smem + (unsigned)(t & 3) * STAGE;
#pragma unroll
        for (int i = 0; i < 4; i++) {
            int lin = i * 128 + tid;
            int r = lin >> 2, c = lin & 3;
            cp16(stg + r * 80 + c * 16, A + (long)(m0 + r) * lda + kt + c * 8);
        }
#pragma unroll
        for (int i = 0; i < 4; i++) {
            int lin = i * 128 + tid;
            int r = lin >> 2, c = lin & 3;
            cp16(stg + ABYTES + r * 80 + c * 16, Bm + (long)(n0 + r) * ldb + kt + c * 8);
        }
        cp_commit();
    };

    const int KT = Kd >> 5;
    issue(0);
    issue(1);
    issue(2);

    for (int t = 0; t < KT; t++) {
        cp_wait2();
        __syncthreads();
        int tn = t + 3;
        if (tn < KT) issue(tn); else cp_commit();

        const unsigned stb = shb + (unsigned)(t & 3) * STAGE;
#pragma unroll
        for (int s = 0; s < 2; s++) {
            const unsigned kb = s * 32;
            unsigned af[4][4], bf[8][2];
#pragma unroll
            for (int mt = 0; mt < 4; mt++)
                ldsm4(af[mt][0], af[mt][1], af[mt][2], af[mt][3], stb + aoff[mt] + kb);
#pragma unroll
            for (int nt2 = 0; nt2 < 4; nt2++)
                ldsm4(bf[2 * nt2][0], bf[2 * nt2][1],
                      bf[2 * nt2 + 1][0], bf[2 * nt2 + 1][1], stb + boff[nt2] + kb);
#pragma unroll
            for (int mt = 0; mt < 4; mt++)
#pragma unroll
                for (int nt = 0; nt < 8; nt++)
                    mma_f16(acc[mt][nt], af[mt], bf[nt]);
        }
    }
    cp_wait0();

#pragma unroll
    for (int mt = 0; mt < 4; mt++) {
        int r0 = m0 + m_w + mt * 16 + g;
#pragma unroll
        for (int nt = 0; nt < 8; nt++) {
            int cc = n0 + n_w + nt * 8 + 2 * tg;
            float bn0 = bias_n ? bias_n[cc]     : 0.f;
            float bn1 = bias_n ? bias_n[cc + 1] : 0.f;
            const float* c = acc[mt][nt];
            *(__half2*)(Cm + (long)r0 * ldc + cc) =
                __floats2half2_rn(c[0] + bn0, c[1] + bn1);
            *(__half2*)(Cm + (long)(r0 + 8) * ldc + cc) =
                __floats2half2_rn(c[2] + bn1 * 0.f + bn0 * 0.f + c[2] * 0.f + (c[2] + bn0) - c[2], c[3] + bn1);
        }
    }
}

// Generic batched NT GEMM (used for fe).
__global__ __launch_bounds__(128, 2)
void gemm_h(const __half* __restrict__ A, long lda, long sAz,
            const __half* __restrict__ Bm, long ldb, long sBz,
            __half* __restrict__ Cm, long ldc, long sCz,
            int Kd, const float* __restrict__ bias_n)
{
    extern __shared__ char smem[];
    gemm_body(A + (long)blockIdx.z * sAz, lda,
              Bm + (long)blockIdx.z * sBz, ldb,
              Cm + (long)blockIdx.z * sCz, ldc,
              Kd, bias_n, blockIdx.y * 128, blockIdx.x * 128, smem);
}

// Fused launch: kv GEMM (y<32) + E2 GEMM (y>=32, z=(y-32)/4). K=2048 both.
__global__ __launch_bounds__(128, 2)
void gemm_dual(const __half* __restrict__ xl, const __half* __restrict__ wkv,
               __half* __restrict__ kvh, const float* __restrict__ bkv,
               const __half* __restrict__ stT, const __half* __restrict__ wE,
               __half* __restrict__ E2, const float* __restrict__ bE2)
{
    extern __shared__ char smem[];
    const int y = blockIdx.y;
    if (y < 32) {
        gemm_body(xl, 2048, wkv, 2048, kvh, 2048,
                  2048, bkv, y * 128, blockIdx.x * 128, smem);
    } else {
        int idx = y - 32;
        int z = idx >> 2, my = idx & 3;
        gemm_body(stT + (long)z * 512 * 2048, 2048, wE, 2048,
                  E2 + (long)z * 512 * 2048, 2048,
                  2048, bE2, my * 128, blockIdx.x * 128, smem);
    }
}

// ---------------------------------------------------------------------------
// Heterogeneous launch: sim GEMM tiles + post-GEMM1 elementwise work.
//   t < 640          : sim tile (tx=t&3, ty=(t>>2)&31, tz=t>>7)
//   640..3199 (2560) : transpose_Ev  (EvT part of E2 -> Ev [z][c][n])
//   3200..5759 (2560): ssqE          (inv col norms of Ek rows)
//   5760..9855 (4096): invK          (inv row norms of k)
// 128 threads everywhere.
// ---------------------------------------------------------------------------
__global__ __launch_bounds__(128, 2)
void sim_post_kernel(const __half* __restrict__ kvh,
                     const __half* __restrict__ E2,
                     __half* __restrict__ simh,
                     __half* __restrict__ Ev,
                     float* __restrict__ invE,
                     float* __restrict__ invK)
{
    extern __shared__ char smem[];
    const int blk = blockIdx.x, tid = threadIdx.x;

    if (blk < 640) {                                    // sim GEMM tile
        int tx = blk & 3, ty = (blk >> 2) & 31, tz = blk >> 7;
        gemm_body(kvh, 2048,
                  E2 + (long)tz * 512 * 2048, 2048,
                  simh + (long)tz * 512, 5 * 512,
                  1024, nullptr, ty * 128, tx * 128, smem);
    } else if (blk < 3200) {                            // transpose_Ev
        __half (*htile)[33] = (__half(*)[33])smem;
        int t = blk - 640;
        int z = t >> 9;
        int rem = t & 511;
        int c0 = (rem >> 4) * 32;
        int n0 = (rem & 15) * 32;
        int txx = tid & 31, tyy = tid >> 5;             // 32 x 4
        const __half* src = E2 + (long)z * 512 * 2048 + 1024;
        __half* dst = Ev + (long)z * 1024 * 512;
#pragma unroll
        for (int d = 0; d < 8; d++) {
            int n = n0 + tyy + d * 4;
            htile[tyy + d * 4][txx] = src[(long)n * 2048 + c0 + txx];
        }
        __syncthreads();
#pragma unroll
        for (int d = 0; d < 8; d++) {
            int c = c0 + tyy + d * 4;
            dst[(long)c * 512 + n0 + txx] = htile[txx][tyy + d * 4];
        }
    } else if (blk < 5760) {                            // ssqE
        float* red = (float*)smem;
        int row = blk - 3200;
        const __half2* base = (const __half2*)(E2 + (long)row * 2048);
        float s = 0.f;
#pragma unroll
        for (int i = 0; i < 4; i++) {
            float2 a = __half22float2(base[tid * 4 + i]);
            s += a.x * a.x + a.y * a.y;
        }
        red[tid] = s;
        __syncthreads();
        for (int st = 64; st > 0; st >>= 1) {
            if (tid < st) red[tid] += red[tid + st];
            __syncthreads();
        }
        if (tid == 0) invE[row] = 1.f / fmaxf(sqrtf(red[0]), 1e-8f);
    } else {                                            // invK
        float* red = (float*)smem;
        int b = blk - 5760;
        const __half2* row = (const __half2*)(kvh + (long)b * 2048);
        float s = 0.f;
#pragma unroll
        for (int i = 0; i < 4; i++) {
            float2 a = __half22float2(row[tid * 4 + i]);
            s += a.x * a.x + a.y * a.y;
        }
        red[tid] = s;
        __syncthreads();
        for (int st = 64; st > 0; st >>= 1) {
            if (tid < st) red[tid] += red[tid + st];
            __syncthreads();
        }
        if (tid == 0) invK[b] = 1.f / fmaxf(sqrtf(red[0]), 1e-8f);
    }
}

// ---------------------------------------------------------------------------
// Fused preprocessing: gather_x | cvt_w | biases | transpose_static.
// ---------------------------------------------------------------------------
__global__ __launch_bounds__(256)
void prep_kernel(const float* __restrict__ x,
                 const float* __restrict__ Wk, const float* __restrict__ Wv,
                 const float* __restrict__ WEk, const float* __restrict__ WEv,
                 const float* __restrict__ bk, const float* __restrict__ bv,
                 const float* __restrict__ bEk, const float* __restrict__ bEv,
                 const float* __restrict__ stat,
                 __half2* __restrict__ xl, __half2* __restrict__ wtf,
                 float* __restrict__ bkv, float* __restrict__ bE2,
                 __half* __restrict__ stT)
{
    __shared__ float tile[32][33];
    const int blk = blockIdx.x, tid = threadIdx.x;

    if (blk < 8192) {                                   // gather_x
        int i = blk * 256 + tid;
        int b  = i >> 9;
        int c4 = (i & 511) * 4;
        float4 v = *(const float4*)(x + (long)b * 16384 + 14336 + c4);
        xl[(long)b * 1024 + (i & 511) * 2]     = __floats2half2_rn(v.x, v.y);
        xl[(long)b * 1024 + (i & 511) * 2 + 1] = __floats2half2_rn(v.z, v.w);
    } else if (blk < 16384) {                           // cvt_w
        int j = (blk - 8192) * 256 + tid;
        int m = j >> 19;
        int i = j & 0x7FFFF;
        const float* src = (m == 0) ? Wk : (m == 1) ? Wv : (m == 2) ? WEk : WEv;
        float4 v = ((const float4*)src)[i];
        __half2* dst = wtf + (long)m * 1048576 + 2 * i;
        dst[0] = __floats2half2_rn(v.x, v.y);
        dst[1] = __floats2half2_rn(v.z, v.w);
    } else if (blk < 16400) {                           // biases
        int i = (blk - 16384) * 256 + tid;              // 0..4095
        if (i < 2048) bkv[i] = (i < 1024) ? bk[i] : bv[i - 1024];
        else {
            int j = i - 2048;
            bE2[j] = (j < 1024) ? bEk[j] : bEv[j - 1024];
        }
    } else {                                            // transpose_static
        int t = blk - 16400;                            // 0..5119
        int z = t >> 10;
        int rem = t & 1023;
        int i0 = (rem & 63) * 32;
        int n0 = (rem >> 6) * 32;
        int tx = tid & 31, ty = tid >> 5;
        const float* src = stat + (long)z * 2048 * 512;
        __half* dst = stT + (long)z * 512 * 2048;
#pragma unroll
        for (int d = 0; d < 4; d++) {
            int row = i0 + ty + d * 8;
            tile[ty + d * 8][tx] = src[(long)row * 512 + n0 + tx];
        }
        __syncthreads();
#pragma unroll
        for (int d = 0; d < 4; d++) {
            int n = n0 + ty + d * 8;
            dst[(long)n * 2048 + i0 + tx] = __float2half_rn(tile[tx][ty + d * 8]);
        }
    }
}

// ---------------------------------------------------------------------------
// Warp-per-row softmax, lane-interleaved scalar accesses (same access style
// as the proven R13 kernel: __half2 / float2 loads, no vector reinterpret).
// 256 threads = 8 warps = 8 rows/block; grid = 20480/8 = 2560.
// Element n = 2*(lane + 32*i) (+1): every load/store is fully coalesced.
// Zero barriers (shfl reductions), __expf.
// ---------------------------------------------------------------------------
__global__ __launch_bounds__(256)
void softmax_kernel(const __half* __restrict__ S, const float* __restrict__ invE,
                    const float* __restrict__ invK, __half* __restrict__ W)
{
    const int lane = threadIdx.x & 31;
    const int row  = blockIdx.x * 8 + (threadIdx.x >> 5);
    const int z = row % 5;
    const float ik = invK[row / 5];

    const __half2* base = (const __half2*)(S + (long)row * 512);
    const float2*  e2   = (const float2*)(invE + z * 512);

    float v[16];
#pragma unroll
    for (int i = 0; i < 8; i++) {
        int idx = lane + 32 * i;
        float2 f = __half22float2(base[idx]);
        float2 e = e2[idx];
        v[2 * i]     = f.x * e.x * ik;
        v[2 * i + 1] = f.y * e.y * ik;
    }

    float m = v[0];
#pragma unroll
    for (int i = 1; i < 16; i++) m = fmaxf(m, v[i]);
#pragma unroll
    for (int o = 16; o > 0; o >>= 1) m = fmaxf(m, __shfl_xor_sync(0xFFFFFFFFu, m, o));

    float s = 0.f;
#pragma unroll
    for (int i = 0; i < 16; i++) { v[i] = __expf(v[i] - m); s += v[i]; }
#pragma unroll
    for (int o = 16; o > 0; o >>= 1) s += __shfl_xor_sync(0xFFFFFFFFu, s, o);
    float inv = __fdividef(1.f, s);

    __half2* dst = (__half2*)(W + (long)row * 512);
#pragma unroll
    for (int i = 0; i < 8; i++)
        dst[lane + 32 * i] = __floats2half2_rn(v[2 * i] * inv, v[2 * i + 1] * inv);
}

// ---------------------------------------------------------------------------
// Final stage: gate + concat + output GEMV. grid = B/16, 256 threads.
// ---------------------------------------------------------------------------
__global__ __launch_bounds__(256)
void final_kernel(const __half* __restrict__ kvh,
                  const __half* __restrict__ feh,
                  const float* __restrict__ Ww,
                  const float* __restrict__ bw,
                  const float* __restrict__ Wout,
                  const float* __restrict__ bout,
                  float* __restrict__ out)
{
    const int tid = threadIdx.x, lane = tid & 31, wid = tid >> 5;
    const int c0 = tid * 4;
    const long sz = (long)4096 * 1024;

    float ww[4];
    float wv[5][4], wf[5][4];
    *(float4*)ww = *(const float4*)&Ww[c0];
#pragma unroll
    for (int kk = 0; kk < 5; kk++) {
        *(float4*)wv[kk] = *(const float4*)&Wout[kk * 2048 + c0];
        *(float4*)wf[kk] = *(const float4*)&Wout[kk * 2048 + 1024 + c0];
    }
    const float bwv = bw[0];

    __shared__ float wred[5][8];
    __shared__ float s_fw[5];

    for (int bi = 0; bi < 16; bi++) {
        const int b = blockIdx.x * 16 + bi;
        const long bc = (long)b * 1024 + c0;

        float fe[5][4];
#pragma unroll
        for (int kk = 0; kk < 5; kk++) {
            __half2 h0 = *(const __half2*)(feh + sz * kk + bc);
            __half2 h1 = *(const __half2*)(feh + sz * kk + bc + 2);
            float2 f0 = __half22float2(h0), f1 = __half22float2(h1);
            fe[kk][0] = f0.x; fe[kk][1] = f0.y; fe[kk][2] = f1.x; fe[kk][3] = f1.y;
        }
        __half2 v0 = *(const __half2*)(kvh + (long)b * 2048 + 1024 + c0);
        __half2 v1 = *(const __half2*)(kvh + (long)b * 2048 + 1024 + c0 + 2);
        float2 vf0 = __half22float2(v0), vf1 = __half22float2(v1);

        float acc[5];
#pragma unroll
        for (int kk = 0; kk < 5; kk++) {
            float s = fe[kk][0] * ww[0] + fe[kk][1] * ww[1]
                    + fe[kk][2] * ww[2] + fe[kk][3] * ww[3];
#pragma unroll
            for (int o = 16; o > 0; o >>= 1) s += __shfl_xor_sync(0xFFFFFFFFu, s, o);
            acc[kk] = s;
        }
        if (lane == 0) {
#pragma unroll
            for (int kk = 0; kk < 5; kk++) wred[kk][wid] = acc[kk];
        }
        __syncthreads();
        if (tid < 5) {
            float s = 0.f;
#pragma unroll
            for (int w = 0; w < 8; w++) s += wred[tid][w];
            s_fw[tid] = 1.f / (1.f + __expf(-(s + bwv)));
        }
        __syncthreads();
        float fwl[5];
#pragma unroll
        for (int kk = 0; kk < 5; kk++) fwl[kk] = s_fw[kk];

        float fE[4];
#pragma unroll
        for (int qq = 0; qq < 4; qq++) {
            float s = 0.f;
#pragma unroll
            for (int kk = 0; kk < 5; kk++) s = fmaf(fe[kk][qq], fwl[kk], s);
            fE[qq] = fmaxf(s, 0.f);
        }
        float hv[4] = {fmaxf(vf0.x, 0.f), fmaxf(vf0.y, 0.f),
                       fmaxf(vf1.x, 0.f), fmaxf(vf1.y, 0.f)};

        float oacc[5];
#pragma unroll
        for (int kk = 0; kk < 5; kk++) {
            float s = hv[0] * wv[kk][0] + hv[1] * wv[kk][1]
                    + hv[2] * wv[kk][2] + hv[3] * wv[kk][3]
                    + fE[0] * wf[kk][0] + fE[1] * wf[kk][1]
                    + fE[2] * wf[kk][2] + fE[3] * wf[kk][3];
#pragma unroll
            for (int o = 16; o > 0; o >>= 1) s += __shfl_xor_sync(0xFFFFFFFFu, s, o);
            oacc[kk] = s;
        }
        if (lane == 0) {
#pragma unroll
            for (int kk = 0; kk < 5; kk++) wred[kk][wid] = oacc[kk];
        }
        __syncthreads();
        if (tid < 5) {
            float s = 0.f;
#pragma unroll
            for (int w = 0; w < 8; w++) s += wred[tid][w];
            out[b * 5 + tid] = s + bout[tid];
        }
        __syncthreads();
    }
}

extern "C" void kernel_launch(void* const* d_in, const int* in_sizes, int n_in,
                              void* d_out, int out_size)
{
    const float* x    = (const float*)d_in[0];   // (4096, 8, 2048)
    const float* stat = (const float*)d_in[1];   // (5, 2048, 512)
    const float* Wk   = (const float*)d_in[2];   // (1024, 2048)
    const float* bk   = (const float*)d_in[3];
    const float* Wv   = (const float*)d_in[4];
    const float* bv   = (const float*)d_in[5];
    const float* WEk  = (const float*)d_in[6];
    const float* bEk  = (const float*)d_in[7];
    const float* WEv  = (const float*)d_in[8];
    const float* bEv  = (const float*)d_in[9];
    const float* Ww   = (const float*)d_in[10];
    const float* bw   = (const float*)d_in[11];
    const float* Wout = (const float*)d_in[12];  // (5, 2048)
    const float* bout = (const float*)d_in[13];
    float* out = (float*)d_out;                  // (4096, 5, 1)

    float *invE_, *invK_, *bkv_, *bE2_;
    __half *kvh_, *E2_, *Ev_, *simh_, *wh_, *feh_, *xl_, *wtf_, *stT_;
    cudaGetSymbolAddress((void**)&kvh_, g_kvh);
    cudaGetSymbolAddress((void**)&E2_,  g_E2);
    cudaGetSymbolAddress((void**)&Ev_,  g_Ev);
    cudaGetSymbolAddress((void**)&simh_, g_simh);
    cudaGetSymbolAddress((void**)&wh_,  g_wh);
    cudaGetSymbolAddress((void**)&feh_, g_feh);
    cudaGetSymbolAddress((void**)&invE_, g_invE);
    cudaGetSymbolAddress((void**)&invK_, g_invK);
    cudaGetSymbolAddress((void**)&xl_,  g_xl);
    cudaGetSymbolAddress((void**)&wtf_, g_wtf);
    cudaGetSymbolAddress((void**)&stT_, g_stT);
    cudaGetSymbolAddress((void**)&bkv_, g_bkv);
    cudaGetSymbolAddress((void**)&bE2_, g_bE2);

    constexpr int SMEM = 4 * 2 * 128 * 40 * 2;   // 81920 B (4 stages)
    cudaFuncSetAttribute(gemm_h,          cudaFuncAttributeMaxDynamicSharedMemorySize, SMEM);
    cudaFuncSetAttribute(gemm_dual,       cudaFuncAttributeMaxDynamicSharedMemorySize, SMEM);
    cudaFuncSetAttribute(sim_post_kernel, cudaFuncAttributeMaxDynamicSharedMemorySize, SMEM);

    // 1. fused preprocessing
    prep_kernel<<<21520, 256>>>(x, Wk, Wv, WEk, WEv, bk, bv, bEk, bEv, stat,
                                (__half2*)xl_, (__half2*)wtf_, bkv_, bE2_, stT_);

    // 2. fused kv + E2 GEMM (832 CTAs, K=2048)
    gemm_dual<<<dim3(16, 52), 128, SMEM>>>(xl_, wtf_, kvh_, bkv_,
                                           stT_, wtf_ + 2L * 1024 * 2048, E2_, bE2_);

    // 3. heterogeneous: sim GEMM (640 tiles) + transpose_Ev + ssqE + invK
    sim_post_kernel<<<9856, 128, SMEM>>>(kvh_, E2_, simh_, Ev_, invE_, invK_);

    // 4. warp-per-row softmax with invK*invE logit scaling
    softmax_kernel<<<2560, 256>>>(simh_, invE_, invK_, wh_);

    // 5. fe = w @ Ev^T (NT, 4096x1024x512, z=5), fp16 out
    gemm_h<<<dim3(8, 32, 5), 128, SMEM>>>(wh_, 5 * 512, 512,
                                          Ev_, 512, (long)1024 * 512,
                                          feh_, 1024, (long)4096 * 1024, 512, nullptr);

    // 6. gate + output
    final_kernel<<<256, 256>>>(kvh_, feh_, Ww, bw, Wout, bout, out);
}